// round 15
// baseline (speedup 1.0000x reference)
#include <cuda_runtime.h>
#include <cuda_bf16.h>
#include <cstdint>
#include <math.h>

#define Bsz 2
#define Lseq 4096
#define Emb 1024
#define Hh 16
#define Ff 4608
#define CHUNK 128
#define NC (Lseq / CHUNK)          // 32
#define NTOK 8192
#define BHn 32
#define NCB (NC * BHn)             // 1024

// ---------------- scratch ----------------
__device__ float g_h[NTOK * Emb];          // tf32-rounded
__device__ float g_qkv[NTOK * 3 * Emb];
__device__ float g_attn[NTOK * Emb];       // tf32-rounded
__device__ float g_x2[NTOK * Emb];
__device__ float g_h2[NTOK * Emb];         // fp32 (dp path)
__device__ float g_h2r[NTOK * Emb];        // tf32-rounded
__device__ float g_gate[NTOK * Ff];
__device__ float g_up[NTOK * Ff];
__device__ float g_hidden[NTOK * Ff];      // tf32-rounded
__device__ float g_KV[NCB * 64 * 64];
__device__ float g_Ksum[NCB * 64];
__device__ float g_Sst[NCB * 64 * 64];
__device__ float g_Zst[NCB * 64];
__device__ float g_part[64 * Emb];
__device__ float g_xmean[Bsz * Emb];
__device__ int   g_size[1];
__device__ float g_invfreq[32];
// tf32-rounded TRANSPOSED weights [N][K]
__device__ float g_wqkvT[3 * Emb * Emb];
__device__ float g_woutT[Emb * Emb];
__device__ float g_wgateT[Ff * Emb];
__device__ float g_wupT[Ff * Emb];
__device__ float g_wdownT[Emb * Ff];

// ---------------- helpers ----------------
__device__ __forceinline__ float blockReduceSum(float v) {
    __shared__ float red[32];
    #pragma unroll
    for (int o = 16; o > 0; o >>= 1) v += __shfl_down_sync(0xffffffffu, v, o);
    int lane = threadIdx.x & 31, w = threadIdx.x >> 5;
    if (lane == 0) red[w] = v;
    __syncthreads();
    int nw = blockDim.x >> 5;
    if (w == 0) {
        v = (lane < nw) ? red[lane] : 0.f;
        #pragma unroll
        for (int o = 16; o > 0; o >>= 1) v += __shfl_down_sync(0xffffffffu, v, o);
        if (lane == 0) red[0] = v;
    }
    __syncthreads();
    return red[0];
}
__device__ __forceinline__ float to_tf32(float x) {
    uint32_t u;
    asm("cvt.rna.tf32.f32 %0, %1;" : "=r"(u) : "f"(x));
    return __uint_as_float(u);
}
__device__ __forceinline__ void mma_tf32(
    float& d0, float& d1, float& d2, float& d3,
    float a0, float a1, float a2, float a3, float b0, float b1) {
    uint32_t A0 = __float_as_uint(a0), A1 = __float_as_uint(a1);
    uint32_t A2 = __float_as_uint(a2), A3 = __float_as_uint(a3);
    uint32_t B0 = __float_as_uint(b0), B1 = __float_as_uint(b1);
    asm("mma.sync.aligned.m16n8k8.row.col.f32.tf32.tf32.f32 "
        "{%0,%1,%2,%3}, {%4,%5,%6,%7}, {%8,%9}, {%0,%1,%2,%3};"
        : "+f"(d0), "+f"(d1), "+f"(d2), "+f"(d3)
        : "r"(A0), "r"(A1), "r"(A2), "r"(A3), "r"(B0), "r"(B1));
}
__device__ __forceinline__ uint32_t smem_u32(const void* p) {
    uint32_t a;
    asm("{ .reg .u64 t; cvta.to.shared.u64 t, %1; cvt.u32.u64 %0, t; }" : "=r"(a) : "l"(p));
    return a;
}
__device__ __forceinline__ void cpa8(uint32_t dst, const float* src) {
    asm volatile("cp.async.ca.shared.global [%0], [%1], 8;" :: "r"(dst), "l"(src));
}
#define CPA_COMMIT() asm volatile("cp.async.commit_group;" ::: "memory")
#define CPA_WAIT2()  asm volatile("cp.async.wait_group 2;" ::: "memory")

__global__ void init_invfreq_kernel() {
    int i = threadIdx.x;
    if (i < 32) g_invfreq[i] = (float)exp(-((double)i / 32.0) * log(10000.0));
}

// W[K][N] -> T[N][K], tf32-rounded
__global__ void __launch_bounds__(256) transpose_round_kernel(
    const float* __restrict__ W, float* __restrict__ T, int K, int N) {
    __shared__ float t[32][33];
    int n0 = blockIdx.x * 32, k0 = blockIdx.y * 32;
    int tx = threadIdx.x & 31, ty = threadIdx.x >> 5;
    #pragma unroll
    for (int r = ty; r < 32; r += 8) t[r][tx] = W[(size_t)(k0 + r) * N + n0 + tx];
    __syncthreads();
    #pragma unroll
    for (int r = ty; r < 32; r += 8)
        T[(size_t)(n0 + r) * K + k0 + tx] = to_tf32(t[tx][r]);
}

// rms_norm: optional fp32 out + tf32-rounded out
__global__ void __launch_bounds__(256) rmsnorm_kernel(const float* __restrict__ x,
    const float* __restrict__ g, float* __restrict__ out, float* __restrict__ out_r) {
    int row = blockIdx.x, tid = threadIdx.x;
    float4 v = ((const float4*)(x + (size_t)row * Emb))[tid];
    if (!isfinite(v.x)) v.x = 0.f;
    if (!isfinite(v.y)) v.y = 0.f;
    if (!isfinite(v.z)) v.z = 0.f;
    if (!isfinite(v.w)) v.w = 0.f;
    float tot = blockReduceSum(v.x * v.x + v.y * v.y + v.z * v.z + v.w * v.w);
    float rms = sqrtf(tot * (1.f / Emb) + 1e-6f);
    rms = fminf(fmaxf(rms, 1e-6f), 1e6f);
    float inv = 1.f / rms;
    float4 gg = ((const float4*)g)[tid];
    float4 o = make_float4(v.x * inv * gg.x, v.y * inv * gg.y, v.z * inv * gg.z, v.w * inv * gg.w);
    if (out) ((float4*)(out + (size_t)row * Emb))[tid] = o;
    if (out_r) {
        float4 r = make_float4(to_tf32(o.x), to_tf32(o.y), to_tf32(o.z), to_tf32(o.w));
        ((float4*)(out_r + (size_t)row * Emb))[tid] = r;
    }
}

// ---------------- tf32 GEMM, cp.async 4-slot / 3-deep pipeline ----------------
// C[M,N] = A[M,K] @ Bt[N,K]^T (+res). Operands pre-rounded tf32.
// Block 128x128xk16; 8 warps 4Mx2N; warp tile 32x64 m16n8k8.
// Smem per slot: A 8KB + B 8KB, [row][k] with 8B-chunk XOR swizzle
//   addr(r,k) = r*64 + (((k>>1) ^ (r&7))<<3) + (k&1)*4  -> fragment LDS conflict-free,
//   all fragment offsets loop-invariant per thread (base+imm).
#define GSM 65536
__global__ void __launch_bounds__(256, 2) tf32gemm_kernel(
    const float* __restrict__ A, const float* __restrict__ Bt, float* __restrict__ C,
    int M, int N, int K,
    const float* __restrict__ residual,
    const int* __restrict__ ncap, const int* __restrict__ kcap) {
    const int n0 = blockIdx.x * 128, m0 = blockIdx.y * 128;
    if (ncap && n0 >= *ncap) return;
    int kend = K;
    if (kcap) {
        int kc = (*kcap + 15) & ~15;
        if (kc < 16) kc = 16;
        if (kc < kend) kend = kc;
    }
    const int nk = kend >> 4;

    extern __shared__ float smf[];
    uint32_t sb = smem_u32(smf);
    const int tid = threadIdx.x, lane = tid & 31, warp = tid >> 5;
    const int wm = (warp & 3) * 32, wn = (warp >> 2) * 64;
    const int g = lane >> 2, t = lane & 3;

    auto load_stage = [&](int s, int kk) {
        uint32_t abase = sb + (uint32_t)s * 16384u;
        uint32_t bbase = abase + 8192u;
        #pragma unroll
        for (int it = 0; it < 4; it++) {
            int idx = tid + it * 256;
            int m = idx >> 3, c = idx & 7;
            cpa8(abase + (uint32_t)(m * 64 + ((c ^ (m & 7)) << 3)),
                 A + (size_t)(m0 + m) * K + kk + c * 2);
        }
        #pragma unroll
        for (int it = 0; it < 4; it++) {
            int idx = tid + it * 256;
            int n = idx >> 3, c = idx & 7;
            cpa8(bbase + (uint32_t)(n * 64 + ((c ^ (n & 7)) << 3)),
                 Bt + (size_t)(n0 + n) * K + kk + c * 2);
        }
    };

    float acc[2][8][4];
    #pragma unroll
    for (int mi = 0; mi < 2; mi++)
        #pragma unroll
        for (int ni = 0; ni < 8; ni++)
            #pragma unroll
            for (int r = 0; r < 4; r++) acc[mi][ni][r] = 0.f;

    auto compute = [&](int s) {
        const float* Ab = smf + s * 4096;
        const float* Bb = Ab + 2048;
        #pragma unroll
        for (int ks = 0; ks < 2; ks++) {
            float af[2][4], bf[8][2];
            #pragma unroll
            for (int mi = 0; mi < 2; mi++)
                #pragma unroll
                for (int r = 0; r < 4; r++) {
                    int m = wm + mi * 16 + g + (r & 1) * 8;
                    int k = t + (r >> 1) * 4 + ks * 8;
                    af[mi][r] = Ab[m * 16 + (((k >> 1) ^ (m & 7)) << 1) + (k & 1)];
                }
            #pragma unroll
            for (int ni = 0; ni < 8; ni++)
                #pragma unroll
                for (int r = 0; r < 2; r++) {
                    int n = wn + ni * 8 + g;
                    int k = t + r * 4 + ks * 8;
                    bf[ni][r] = Bb[n * 16 + (((k >> 1) ^ (n & 7)) << 1) + (k & 1)];
                }
            #pragma unroll
            for (int mi = 0; mi < 2; mi++)
                #pragma unroll
                for (int ni = 0; ni < 8; ni++)
                    mma_tf32(acc[mi][ni][0], acc[mi][ni][1], acc[mi][ni][2], acc[mi][ni][3],
                             af[mi][0], af[mi][1], af[mi][2], af[mi][3],
                             bf[ni][0], bf[ni][1]);
        }
    };

    // prologue: 3 chunks in flight
    #pragma unroll
    for (int s = 0; s < 3; s++) {
        if (s < nk) load_stage(s, s * 16);
        CPA_COMMIT();
    }
    for (int i = 0; i < nk; i++) {
        CPA_WAIT2();
        __syncthreads();
        int nx = i + 3;
        if (nx < nk) load_stage(nx & 3, nx * 16);
        CPA_COMMIT();
        compute(i & 3);
    }

    // epilogue
    #pragma unroll
    for (int mi = 0; mi < 2; mi++) {
        #pragma unroll
        for (int ni = 0; ni < 8; ni++) {
            int row0 = m0 + wm + mi * 16 + g;
            int col = n0 + wn + ni * 8 + t * 2;
            float2 v0 = make_float2(acc[mi][ni][0], acc[mi][ni][1]);
            float2 v1 = make_float2(acc[mi][ni][2], acc[mi][ni][3]);
            if (residual) {
                float2 r0 = *(const float2*)&residual[(size_t)row0 * N + col];
                float2 r1 = *(const float2*)&residual[(size_t)(row0 + 8) * N + col];
                v0.x += r0.x; v0.y += r0.y;
                v1.x += r1.x; v1.y += r1.y;
            }
            *(float2*)&C[(size_t)row0 * N + col] = v0;
            *(float2*)&C[(size_t)(row0 + 8) * N + col] = v1;
        }
    }
}

// ---------------- RoPE + elu+1 ----------------
__global__ void __launch_bounds__(256) rope_elu_kernel(float* __restrict__ qkv) {
    int idx = blockIdx.x * blockDim.x + threadIdx.x;
    if (idx >= NTOK * Hh * 32) return;
    int p = idx & 31, h = (idx >> 5) & 15, t = idx >> 9;
    int l = t & (Lseq - 1), d0 = 2 * p;
    float a0 = (float)l * g_invfreq[d0 & 31];
    float a1 = (float)l * g_invfreq[(d0 + 1) & 31];
    float s0, c0, s1, c1;
    sincosf(a0, &s0, &c0);
    sincosf(a1, &s1, &c1);
    size_t base = (size_t)t * 3072 + h * 64 + d0;
    #pragma unroll
    for (int s = 0; s < 2; s++) {
        float va = qkv[base + s * 1024], vb = qkv[base + s * 1024 + 1];
        float r0 = va * c0 - vb * s0, r1 = vb * c1 + va * s1;
        r0 = (r0 > 0.f) ? (r0 + 1.f) : expf(r0);
        r1 = (r1 > 0.f) ? (r1 + 1.f) : expf(r1);
        qkv[base + s * 1024] = r0;
        qkv[base + s * 1024 + 1] = r1;
    }
}

// ---------------- per-chunk K^T V and sum(K) (CHUNK=128) ----------------
__global__ void __launch_bounds__(256) chunkstats_kernel() {
    int cb = blockIdx.x, bh = cb & 31, c = cb >> 5;
    int b = bh >> 4, h = bh & 15, tid = threadIdx.x;
    __shared__ __align__(16) float Ks[32][64], Vs[32][64];
    const int d0 = (tid >> 4) * 4, e0 = (tid & 15) * 4;
    float acc[4][4];
    #pragma unroll
    for (int i = 0; i < 4; i++)
        #pragma unroll
        for (int j = 0; j < 4; j++) acc[i][j] = 0.f;
    float ks = 0.f;
    for (int lt = 0; lt < CHUNK; lt += 32) {
        int idx = tid;
        #pragma unroll
        for (int it = 0; it < 2; it++, idx += 256) {
            int r = idx >> 4, c4 = (idx & 15) << 2;
            size_t base = ((size_t)(b * Lseq + c * CHUNK + lt + r)) * 3072 + h * 64 + c4;
            *(float4*)&Ks[r][c4] = *(const float4*)&g_qkv[base + 1024];
            *(float4*)&Vs[r][c4] = *(const float4*)&g_qkv[base + 2048];
        }
        __syncthreads();
        #pragma unroll 4
        for (int ll = 0; ll < 32; ll++) {
            float kd[4], ve[4];
            #pragma unroll
            for (int i = 0; i < 4; i++) kd[i] = Ks[ll][d0 + i];
            #pragma unroll
            for (int j = 0; j < 4; j++) ve[j] = Vs[ll][e0 + j];
            #pragma unroll
            for (int i = 0; i < 4; i++)
                #pragma unroll
                for (int j = 0; j < 4; j++) acc[i][j] += kd[i] * ve[j];
        }
        if (tid < 64) {
            #pragma unroll 4
            for (int ll = 0; ll < 32; ll++) ks += Ks[ll][tid];
        }
        __syncthreads();
    }
    size_t off = (size_t)cb * 4096;
    #pragma unroll
    for (int i = 0; i < 4; i++)
        #pragma unroll
        for (int j = 0; j < 4; j++) g_KV[off + (d0 + i) * 64 + e0 + j] = acc[i][j];
    if (tid < 64) g_Ksum[(size_t)cb * 64 + tid] = ks;
}

__global__ void __launch_bounds__(256) prefix_kernel() {
    int bh = blockIdx.x, tid = threadIdx.x;
    float acc[16];
    #pragma unroll
    for (int t = 0; t < 16; t++) acc[t] = 0.f;
    for (int c = 0; c < NC; c++) {
        size_t off = (size_t)(c * 32 + bh) * 4096;
        #pragma unroll
        for (int t = 0; t < 16; t++) {
            int e = tid + t * 256;
            g_Sst[off + e] = acc[t];
            acc[t] += g_KV[off + e];
        }
    }
    if (tid < 64) {
        float az = 0.f;
        for (int c = 0; c < NC; c++) {
            size_t off = (size_t)(c * 32 + bh) * 64 + tid;
            g_Zst[off] = az;
            az += g_Ksum[off];
        }
    }
}

// ---------------- attention output (CHUNK=128, 128 threads) ----------------
__global__ void __launch_bounds__(128) attn_out_kernel() {
    int cb = blockIdx.x, bh = cb & 31, c = cb >> 5;
    int b = bh >> 4, h = bh & 15, tid = threadIdx.x;
    int i = tid, l = c * CHUNK + i;
    __shared__ __align__(16) float sm[2 * 64 * 64];
    __shared__ float Zs[64];
    {
        size_t off = (size_t)cb * 4096;
        for (int t = tid; t < 4096; t += 128) sm[t] = g_Sst[off + t];
        if (tid < 64) Zs[tid] = g_Zst[(size_t)cb * 64 + tid];
    }
    size_t qbase = ((size_t)(b * Lseq + l)) * 3072 + h * 64;
    float q[64];
    #pragma unroll
    for (int d = 0; d < 64; d += 4) {
        float4 v = *(const float4*)&g_qkv[qbase + d];
        q[d] = v.x; q[d + 1] = v.y; q[d + 2] = v.z; q[d + 3] = v.w;
    }
    __syncthreads();
    float num[64];
    #pragma unroll
    for (int e = 0; e < 64; e++) num[e] = 0.f;
    float den = 0.f;
    for (int d = 0; d < 64; d++) {
        float qd = __ldg(&g_qkv[qbase + d]);
        den += qd * Zs[d];
        const float* Srow = &sm[d * 64];
        #pragma unroll
        for (int e = 0; e < 64; e++) num[e] += qd * Srow[e];
    }
    __syncthreads();
    float* Ksm = sm;
    float* Vsm = sm + 4096;
    for (int jt = 0; jt < CHUNK; jt += 64) {
        for (int idx = tid; idx < 1024; idx += 128) {
            int r = idx >> 4, c4 = (idx & 15) << 2;
            size_t base = ((size_t)(b * Lseq + c * CHUNK + jt + r)) * 3072 + h * 64 + c4;
            *(float4*)&Ksm[r * 64 + c4] = *(const float4*)&g_qkv[base + 1024];
            *(float4*)&Vsm[r * 64 + c4] = *(const float4*)&g_qkv[base + 2048];
        }
        __syncthreads();
        int jmax = i - jt + 1;
        if (jmax > 64) jmax = 64;
        for (int j = 0; j < jmax; j++) {
            const float* kr = &Ksm[j * 64];
            float s = 0.f;
            #pragma unroll
            for (int d = 0; d < 64; d++) s += q[d] * kr[d];
            den += s;
            const float* vr = &Vsm[j * 64];
            #pragma unroll
            for (int e = 0; e < 64; e++) num[e] += s * vr[e];
        }
        __syncthreads();
    }
    float invd = 1.f / fmaxf(den, 1e-6f);
    size_t obase = ((size_t)(b * Lseq + l)) * Emb + h * 64;
    #pragma unroll
    for (int e = 0; e < 64; e += 4) {
        float4 v = make_float4(to_tf32(num[e] * invd), to_tf32(num[e + 1] * invd),
                               to_tf32(num[e + 2] * invd), to_tf32(num[e + 3] * invd));
        *(float4*)&g_attn[obase + e] = v;
    }
}

// ---------------- column-mean / dp scalar ----------------
__global__ void colmean_part_kernel() {
    int col = blockIdx.x * 256 + threadIdx.x, b = blockIdx.y, z = blockIdx.z;
    float s = 0.f;
    size_t base = ((size_t)b * Lseq + z * 128) * Emb + col;
    #pragma unroll 8
    for (int r = 0; r < 128; r++) s += g_h2[base + (size_t)r * Emb];
    g_part[(z * 2 + b) * Emb + col] = s;
}
__global__ void colmean_final_kernel() {
    int idx = blockIdx.x * 256 + threadIdx.x;
    float s = 0.f;
    for (int z = 0; z < 32; z++) s += g_part[(z * 2 + (idx >> 10)) * Emb + (idx & 1023)];
    g_xmean[idx] = s * (1.f / (float)Lseq);
}
__global__ void __launch_bounds__(256) dp_kernel(const float* __restrict__ w1,
                                                 const float* __restrict__ w2) {
    __shared__ float t[256];
    __shared__ float ratios[2];
    int tid = threadIdx.x;
    for (int b = 0; b < Bsz; b++) {
        float acc = 0.f;
        for (int e = 0; e < Emb; e++) acc += g_xmean[b * Emb + e] * w1[e * 256 + tid];
        t[tid] = acc / (1.f + expf(-acc));
        __syncthreads();
        if (tid == 0) {
            float s = 0.f;
            for (int j = 0; j < 256; j++) s += t[j] * w2[j];
            float r = 1.f / (1.f + expf(-s));
            ratios[b] = fminf(fmaxf(1.f + (r - 0.5f), 0.5f), 1.5f);
        }
        __syncthreads();
    }
    if (tid == 0) {
        int sz = (int)floorf(3072.f * (ratios[0] + ratios[1]) * 0.5f);
        g_size[0] = sz < 1 ? 1 : sz;
    }
}

// ---------------- combine -> tf32-rounded hidden ----------------
__global__ void __launch_bounds__(256) combine_kernel(const float* __restrict__ ghid) {
    int row = blockIdx.x, tid = threadIdx.x;
    int sz = g_size[0];
    __shared__ float buf[Ff];
    float local = 0.f;
    for (int c = tid; c < Ff; c += 256) {
        float hv = 0.f;
        if (c < sz) {
            float gv = g_gate[(size_t)row * Ff + c];
            float uv = g_up[(size_t)row * Ff + c];
            hv = (gv / (1.f + expf(-gv))) * uv;
            if (!isfinite(hv)) hv = 0.f;
        }
        buf[c] = hv;
        local += hv * hv;
    }
    float tot = blockReduceSum(local);
    float rms = sqrtf(tot / (float)sz + 1e-6f);
    rms = fminf(fmaxf(rms, 1e-6f), 1e6f);
    float inv = 1.f / rms;
    __syncthreads();
    for (int c = tid; c < Ff; c += 256) {
        float v = (c < sz) ? to_tf32(buf[c] * inv * ghid[c]) : 0.f;
        g_hidden[(size_t)row * Ff + c] = v;
    }
}

// ---------------- host launch ----------------
extern "C" void kernel_launch(void* const* d_in, const int* in_sizes, int n_in,
                              void* d_out, int out_size) {
    const float* x = (const float*)d_in[0];
    const float* w_qkv = (const float*)d_in[1];
    const float* w_out = (const float*)d_in[2];
    const float* g1 = (const float*)d_in[3];
    const float* g2 = (const float*)d_in[4];
    const float* w_dp1 = (const float*)d_in[5];
    const float* w_dp2 = (const float*)d_in[6];
    const float* w_gate = (const float*)d_in[7];
    const float* w_up = (const float*)d_in[8];
    const float* w_down = (const float*)d_in[9];
    const float* ghid = (const float*)d_in[10];
    float* out = (float*)d_out;

    float *p_h, *p_qkv, *p_attn, *p_x2, *p_h2, *p_h2r, *p_gate, *p_up, *p_hidden;
    float *wqT, *woT, *wgT, *wuT, *wdT;
    int* p_size;
    cudaGetSymbolAddress((void**)&p_h, g_h);
    cudaGetSymbolAddress((void**)&p_qkv, g_qkv);
    cudaGetSymbolAddress((void**)&p_attn, g_attn);
    cudaGetSymbolAddress((void**)&p_x2, g_x2);
    cudaGetSymbolAddress((void**)&p_h2, g_h2);
    cudaGetSymbolAddress((void**)&p_h2r, g_h2r);
    cudaGetSymbolAddress((void**)&p_gate, g_gate);
    cudaGetSymbolAddress((void**)&p_up, g_up);
    cudaGetSymbolAddress((void**)&p_hidden, g_hidden);
    cudaGetSymbolAddress((void**)&wqT, g_wqkvT);
    cudaGetSymbolAddress((void**)&woT, g_woutT);
    cudaGetSymbolAddress((void**)&wgT, g_wgateT);
    cudaGetSymbolAddress((void**)&wuT, g_wupT);
    cudaGetSymbolAddress((void**)&wdT, g_wdownT);
    cudaGetSymbolAddress((void**)&p_size, g_size);

    cudaFuncSetAttribute(tf32gemm_kernel, cudaFuncAttributeMaxDynamicSharedMemorySize, GSM);

    init_invfreq_kernel<<<1, 32>>>();
    // transpose+round weights -> [N][K] tf32
    transpose_round_kernel<<<dim3(3 * Emb / 32, Emb / 32), 256>>>(w_qkv, wqT, Emb, 3 * Emb);
    transpose_round_kernel<<<dim3(Emb / 32, Emb / 32), 256>>>(w_out, woT, Emb, Emb);
    transpose_round_kernel<<<dim3(Ff / 32, Emb / 32), 256>>>(w_gate, wgT, Emb, Ff);
    transpose_round_kernel<<<dim3(Ff / 32, Emb / 32), 256>>>(w_up, wuT, Emb, Ff);
    transpose_round_kernel<<<dim3(Emb / 32, Ff / 32), 256>>>(w_down, wdT, Ff, Emb);

    // h = tf32(rms_norm(x, g1))
    rmsnorm_kernel<<<NTOK, 256>>>(x, g1, nullptr, p_h);
    // qkv = h @ w_qkv
    tf32gemm_kernel<<<dim3(3 * Emb / 128, NTOK / 128), 256, GSM>>>(
        p_h, wqT, p_qkv, NTOK, 3 * Emb, Emb, nullptr, nullptr, nullptr);
    rope_elu_kernel<<<(NTOK * Hh * 32 + 255) / 256, 256>>>(p_qkv);
    // linear attention
    chunkstats_kernel<<<NCB, 256>>>();
    prefix_kernel<<<BHn, 256>>>();
    attn_out_kernel<<<NCB, 128>>>();
    // x2 = x + attn @ w_out
    tf32gemm_kernel<<<dim3(Emb / 128, NTOK / 128), 256, GSM>>>(
        p_attn, woT, p_x2, NTOK, Emb, Emb, x, nullptr, nullptr);
    // h2 (fp32 for dp path) + h2r (tf32)
    rmsnorm_kernel<<<NTOK, 256>>>(p_x2, g2, p_h2, p_h2r);
    colmean_part_kernel<<<dim3(Emb / 256, Bsz, 32), 256>>>();
    colmean_final_kernel<<<(Bsz * Emb) / 256, 256>>>();
    dp_kernel<<<1, 256>>>(w_dp1, w_dp2);
    // gate/up with N-cap
    tf32gemm_kernel<<<dim3(Ff / 128, NTOK / 128), 256, GSM>>>(
        p_h2r, wgT, p_gate, NTOK, Ff, Emb, nullptr, p_size, nullptr);
    tf32gemm_kernel<<<dim3(Ff / 128, NTOK / 128), 256, GSM>>>(
        p_h2r, wuT, p_up, NTOK, Ff, Emb, nullptr, p_size, nullptr);
    combine_kernel<<<NTOK, 256>>>(ghid);
    // out = x2 + hidden @ w_down (K-cap)
    tf32gemm_kernel<<<dim3(Emb / 128, NTOK / 128), 256, GSM>>>(
        p_hidden, wdT, out, NTOK, Emb, Ff, p_x2, nullptr, p_size);
}

// round 16
// speedup vs baseline: 1.1335x; 1.1335x over previous
#include <cuda_runtime.h>
#include <cuda_bf16.h>
#include <cstdint>
#include <math.h>

// ---------------- problem constants ----------------
#define Bsz 2
#define Lseq 4096
#define Emb 1024
#define Hh 16
#define Dd 64
#define Ff 4608
#define CHUNK 128
#define NC (Lseq / CHUNK)          // 32
#define NTOK (Bsz * Lseq)          // 8192
#define BHn (Bsz * Hh)             // 32
#define NCB (NC * BHn)             // 1024

// ---------------- scratch (static device arrays; allocation-free) ----------------
__device__ float g_h[NTOK * Emb];
__device__ float g_qkv[NTOK * 3 * Emb];
__device__ float g_attn[NTOK * Emb];
__device__ float g_x2[NTOK * Emb];
__device__ float g_h2[NTOK * Emb];
__device__ float g_gate[NTOK * Ff];
__device__ float g_up[NTOK * Ff];
__device__ float g_hidden[NTOK * Ff];
__device__ float g_KV[NCB * Dd * Dd];
__device__ float g_Ksum[NCB * Dd];
__device__ float g_Sst[NCB * Dd * Dd];
__device__ float g_Zst[NCB * Dd];
__device__ float g_part[64 * Emb];
__device__ float g_xmean[Bsz * Emb];
__device__ int   g_size[1];
__device__ float g_invfreq[32];

// ---------------- helpers ----------------
__device__ __forceinline__ float blockReduceSum(float v) {
    __shared__ float red[32];
    #pragma unroll
    for (int o = 16; o > 0; o >>= 1) v += __shfl_down_sync(0xffffffffu, v, o);
    int lane = threadIdx.x & 31, w = threadIdx.x >> 5;
    if (lane == 0) red[w] = v;
    __syncthreads();
    int nw = blockDim.x >> 5;
    if (w == 0) {
        v = (lane < nw) ? red[lane] : 0.f;
        #pragma unroll
        for (int o = 16; o > 0; o >>= 1) v += __shfl_down_sync(0xffffffffu, v, o);
        if (lane == 0) red[0] = v;
    }
    __syncthreads();
    return red[0];
}

__device__ __forceinline__ float to_tf32(float x) {
    uint32_t u;
    asm("cvt.rna.tf32.f32 %0, %1;" : "=r"(u) : "f"(x));
    return __uint_as_float(u);
}

__device__ __forceinline__ void mma_tf32(
    float& d0, float& d1, float& d2, float& d3,
    float a0, float a1, float a2, float a3,
    float b0, float b1) {
    uint32_t A0 = __float_as_uint(a0), A1 = __float_as_uint(a1);
    uint32_t A2 = __float_as_uint(a2), A3 = __float_as_uint(a3);
    uint32_t B0 = __float_as_uint(b0), B1 = __float_as_uint(b1);
    asm("mma.sync.aligned.m16n8k8.row.col.f32.tf32.tf32.f32 "
        "{%0,%1,%2,%3}, {%4,%5,%6,%7}, {%8,%9}, {%0,%1,%2,%3};"
        : "+f"(d0), "+f"(d1), "+f"(d2), "+f"(d3)
        : "r"(A0), "r"(A1), "r"(A2), "r"(A3), "r"(B0), "r"(B1));
}

// ---------------- init: inv_freq table ----------------
__global__ void init_invfreq_kernel() {
    int i = threadIdx.x;
    if (i < 32) g_invfreq[i] = (float)exp(-((double)i / 32.0) * log(10000.0));
}

// ---------------- rms_norm: one block per row ----------------
__global__ void __launch_bounds__(256) rmsnorm_kernel(const float* __restrict__ x,
                                                      const float* __restrict__ g,
                                                      float* __restrict__ out) {
    int row = blockIdx.x;
    int tid = threadIdx.x;
    const float4* xr = (const float4*)(x + (size_t)row * Emb);
    float4 v = xr[tid];
    if (!isfinite(v.x)) v.x = 0.f;
    if (!isfinite(v.y)) v.y = 0.f;
    if (!isfinite(v.z)) v.z = 0.f;
    if (!isfinite(v.w)) v.w = 0.f;
    float s = v.x * v.x + v.y * v.y + v.z * v.z + v.w * v.w;
    float tot = blockReduceSum(s);
    float rms = sqrtf(tot * (1.f / (float)Emb) + 1e-6f);
    rms = fminf(fmaxf(rms, 1e-6f), 1e6f);
    float inv = 1.f / rms;
    float4 gg = ((const float4*)g)[tid];
    float4 o;
    o.x = v.x * inv * gg.x; o.y = v.y * inv * gg.y;
    o.z = v.z * inv * gg.z; o.w = v.w * inv * gg.w;
    ((float4*)(out + (size_t)row * Emb))[tid] = o;
}

// ---------------- tf32 tensor-core GEMM (EXACT R6 winner) ----------------
// Block tile 128x128x16, 8 warps (4M x 2N), warp tile 32x64 via m16n8k8.
// LDSM=136 -> fragment LDS bank = 8t+g: conflict-free.
// Double-buffered smem: one __syncthreads per k-iter; 2 CTAs/SM.
#define LDSM 136
__global__ void __launch_bounds__(256, 2) tf32gemm_kernel(
    const float* __restrict__ A, const float* __restrict__ Bm, float* __restrict__ C,
    int M, int N, int K,
    const float* __restrict__ residual,
    const int* __restrict__ ncap, const int* __restrict__ kcap) {
    const int n0 = blockIdx.x * 128;
    const int m0 = blockIdx.y * 128;
    if (ncap && n0 >= *ncap) return;
    int kend = K;
    if (kcap) {
        int kc = (*kcap + 15) & ~15;
        if (kc < 16) kc = 16;
        if (kc < kend) kend = kc;
    }

    __shared__ __align__(16) float As[2][16 * LDSM];
    __shared__ __align__(16) float Bs[2][16 * LDSM];

    const int tid = threadIdx.x;
    const int lane = tid & 31;
    const int warp = tid >> 5;
    const int wm = (warp & 3) * 32;
    const int wn = (warp >> 2) * 64;
    const int g = lane >> 2;
    const int t = lane & 3;

    const int aRow = tid >> 2;
    const int aCol = (tid & 3) << 2;
    const int bRow = tid >> 5;
    const int bCol = (tid & 31) << 2;

    const float* Ap0 = A + (size_t)(m0 + aRow) * K + aCol;
    const float* Ap1 = A + (size_t)(m0 + aRow + 64) * K + aCol;
    const float* Bp0 = Bm + (size_t)bRow * N + n0 + bCol;
    const float* Bp1 = Bm + (size_t)(bRow + 8) * N + n0 + bCol;

    float acc[2][8][4];
    #pragma unroll
    for (int mi = 0; mi < 2; mi++)
        #pragma unroll
        for (int ni = 0; ni < 8; ni++)
            #pragma unroll
            for (int r = 0; r < 4; r++) acc[mi][ni][r] = 0.f;

    float4 aReg0, aReg1, bReg0, bReg1;

    auto gload = [&](int k) {
        aReg0 = *(const float4*)(Ap0 + k);
        aReg1 = *(const float4*)(Ap1 + k);
        bReg0 = *(const float4*)(Bp0 + (size_t)k * N);
        bReg1 = *(const float4*)(Bp1 + (size_t)k * N);
    };

    auto sstore = [&](int buf) {
        As[buf][(aCol + 0) * LDSM + aRow] = to_tf32(aReg0.x);
        As[buf][(aCol + 1) * LDSM + aRow] = to_tf32(aReg0.y);
        As[buf][(aCol + 2) * LDSM + aRow] = to_tf32(aReg0.z);
        As[buf][(aCol + 3) * LDSM + aRow] = to_tf32(aReg0.w);
        As[buf][(aCol + 0) * LDSM + aRow + 64] = to_tf32(aReg1.x);
        As[buf][(aCol + 1) * LDSM + aRow + 64] = to_tf32(aReg1.y);
        As[buf][(aCol + 2) * LDSM + aRow + 64] = to_tf32(aReg1.z);
        As[buf][(aCol + 3) * LDSM + aRow + 64] = to_tf32(aReg1.w);
        float4 b0 = make_float4(to_tf32(bReg0.x), to_tf32(bReg0.y), to_tf32(bReg0.z), to_tf32(bReg0.w));
        float4 b1 = make_float4(to_tf32(bReg1.x), to_tf32(bReg1.y), to_tf32(bReg1.z), to_tf32(bReg1.w));
        *(float4*)&Bs[buf][bRow * LDSM + bCol] = b0;
        *(float4*)&Bs[buf][(bRow + 8) * LDSM + bCol] = b1;
    };

    auto compute = [&](int buf) {
        const float* Asb = As[buf];
        const float* Bsb = Bs[buf];
        #pragma unroll
        for (int ks = 0; ks < 2; ks++) {
            const int k0 = ks * 8;
            float af[2][4];
            #pragma unroll
            for (int mi = 0; mi < 2; mi++) {
                int mrow = wm + mi * 16 + g;
                af[mi][0] = Asb[(k0 + t) * LDSM + mrow];
                af[mi][1] = Asb[(k0 + t) * LDSM + mrow + 8];
                af[mi][2] = Asb[(k0 + t + 4) * LDSM + mrow];
                af[mi][3] = Asb[(k0 + t + 4) * LDSM + mrow + 8];
            }
            float bf[8][2];
            #pragma unroll
            for (int ni = 0; ni < 8; ni++) {
                int ncol = wn + ni * 8 + g;
                bf[ni][0] = Bsb[(k0 + t) * LDSM + ncol];
                bf[ni][1] = Bsb[(k0 + t + 4) * LDSM + ncol];
            }
            #pragma unroll
            for (int mi = 0; mi < 2; mi++)
                #pragma unroll
                for (int ni = 0; ni < 8; ni++)
                    mma_tf32(acc[mi][ni][0], acc[mi][ni][1], acc[mi][ni][2], acc[mi][ni][3],
                             af[mi][0], af[mi][1], af[mi][2], af[mi][3],
                             bf[ni][0], bf[ni][1]);
        }
    };

    gload(0);
    sstore(0);
    __syncthreads();
    int buf = 0;
    for (int k = 16; k < kend; k += 16) {
        gload(k);
        compute(buf);
        sstore(buf ^ 1);
        __syncthreads();
        buf ^= 1;
    }
    compute(buf);

    #pragma unroll
    for (int mi = 0; mi < 2; mi++) {
        #pragma unroll
        for (int ni = 0; ni < 8; ni++) {
            int row0 = m0 + wm + mi * 16 + g;
            int col = n0 + wn + ni * 8 + t * 2;
            float2 v0 = make_float2(acc[mi][ni][0], acc[mi][ni][1]);
            float2 v1 = make_float2(acc[mi][ni][2], acc[mi][ni][3]);
            if (residual) {
                float2 r0 = *(const float2*)&residual[(size_t)row0 * N + col];
                float2 r1 = *(const float2*)&residual[(size_t)(row0 + 8) * N + col];
                v0.x += r0.x; v0.y += r0.y;
                v1.x += r1.x; v1.y += r1.y;
            }
            *(float2*)&C[(size_t)row0 * N + col] = v0;
            *(float2*)&C[(size_t)(row0 + 8) * N + col] = v1;
        }
    }
}

// ---------------- RoPE + elu+1 on q,k ----------------
__global__ void __launch_bounds__(256) rope_elu_kernel(float* __restrict__ qkv) {
    int idx = blockIdx.x * blockDim.x + threadIdx.x;
    if (idx >= NTOK * Hh * 32) return;
    int p = idx & 31, h = (idx >> 5) & 15, t = idx >> 9;
    int l = t & (Lseq - 1), d0 = 2 * p;
    float a0 = (float)l * g_invfreq[d0 & 31];
    float a1 = (float)l * g_invfreq[(d0 + 1) & 31];
    float s0, c0, s1, c1;
    sincosf(a0, &s0, &c0);
    sincosf(a1, &s1, &c1);
    size_t base = (size_t)t * 3072 + h * 64 + d0;
    #pragma unroll
    for (int s = 0; s < 2; s++) {
        float va = qkv[base + s * 1024], vb = qkv[base + s * 1024 + 1];
        float r0 = va * c0 - vb * s0, r1 = vb * c1 + va * s1;
        r0 = (r0 > 0.f) ? (r0 + 1.f) : expf(r0);
        r1 = (r1 > 0.f) ? (r1 + 1.f) : expf(r1);
        qkv[base + s * 1024] = r0;
        qkv[base + s * 1024 + 1] = r1;
    }
}

// ---------------- per-chunk K^T V and sum(K) (CHUNK=128) ----------------
__global__ void __launch_bounds__(256) chunkstats_kernel() {
    int cb = blockIdx.x, bh = cb & 31, c = cb >> 5;
    int b = bh >> 4, h = bh & 15, tid = threadIdx.x;
    __shared__ __align__(16) float Ks[32][64], Vs[32][64];
    const int d0 = (tid >> 4) * 4, e0 = (tid & 15) * 4;
    float acc[4][4];
    #pragma unroll
    for (int i = 0; i < 4; i++)
        #pragma unroll
        for (int j = 0; j < 4; j++) acc[i][j] = 0.f;
    float ks = 0.f;
    for (int lt = 0; lt < CHUNK; lt += 32) {
        int idx = tid;
        #pragma unroll
        for (int it = 0; it < 2; it++, idx += 256) {
            int r = idx >> 4, c4 = (idx & 15) << 2;
            size_t base = ((size_t)(b * Lseq + c * CHUNK + lt + r)) * 3072 + h * 64 + c4;
            *(float4*)&Ks[r][c4] = *(const float4*)&g_qkv[base + 1024];
            *(float4*)&Vs[r][c4] = *(const float4*)&g_qkv[base + 2048];
        }
        __syncthreads();
        #pragma unroll 4
        for (int ll = 0; ll < 32; ll++) {
            float kd[4], ve[4];
            #pragma unroll
            for (int i = 0; i < 4; i++) kd[i] = Ks[ll][d0 + i];
            #pragma unroll
            for (int j = 0; j < 4; j++) ve[j] = Vs[ll][e0 + j];
            #pragma unroll
            for (int i = 0; i < 4; i++)
                #pragma unroll
                for (int j = 0; j < 4; j++) acc[i][j] += kd[i] * ve[j];
        }
        if (tid < 64) {
            #pragma unroll 4
            for (int ll = 0; ll < 32; ll++) ks += Ks[ll][tid];
        }
        __syncthreads();
    }
    size_t off = (size_t)cb * (Dd * Dd);
    #pragma unroll
    for (int i = 0; i < 4; i++)
        #pragma unroll
        for (int j = 0; j < 4; j++)
            g_KV[off + (d0 + i) * 64 + e0 + j] = acc[i][j];
    if (tid < 64) g_Ksum[(size_t)cb * 64 + tid] = ks;
}

// ---------------- exclusive prefix over NC=32 chunks per (b,h) ----------------
__global__ void __launch_bounds__(256) prefix_kernel() {
    int bh = blockIdx.x, tid = threadIdx.x;
    float acc[16];
    #pragma unroll
    for (int t = 0; t < 16; t++) acc[t] = 0.f;
    for (int c = 0; c < NC; c++) {
        size_t off = (size_t)(c * 32 + bh) * (Dd * Dd);
        #pragma unroll
        for (int t = 0; t < 16; t++) {
            int e = tid + t * 256;
            g_Sst[off + e] = acc[t];
            acc[t] += g_KV[off + e];
        }
    }
    if (tid < 64) {
        float az = 0.f;
        for (int c = 0; c < NC; c++) {
            size_t off = (size_t)(c * 32 + bh) * 64 + tid;
            g_Zst[off] = az;
            az += g_Ksum[off];
        }
    }
}

// ---------------- attention output (CHUNK=128, 128 threads) ----------------
__global__ void __launch_bounds__(128) attn_out_kernel() {
    int cb = blockIdx.x, bh = cb & 31, c = cb >> 5;
    int b = bh >> 4, h = bh & 15, tid = threadIdx.x;
    int i = tid, l = c * CHUNK + i;
    __shared__ __align__(16) float sm[2 * 64 * 64];
    __shared__ float Zs[64];
    {
        size_t off = (size_t)cb * (Dd * Dd);
        for (int t = tid; t < 4096; t += 128) sm[t] = g_Sst[off + t];
        if (tid < 64) Zs[tid] = g_Zst[(size_t)cb * 64 + tid];
    }
    size_t qbase = ((size_t)(b * Lseq + l)) * 3072 + h * 64;
    float q[64];
    #pragma unroll
    for (int d = 0; d < 64; d += 4) {
        float4 v = *(const float4*)&g_qkv[qbase + d];
        q[d] = v.x; q[d + 1] = v.y; q[d + 2] = v.z; q[d + 3] = v.w;
    }
    __syncthreads();
    float num[64];
    #pragma unroll
    for (int e = 0; e < 64; e++) num[e] = 0.f;
    float den = 0.f;
    for (int d = 0; d < 64; d++) {
        float qd = __ldg(&g_qkv[qbase + d]);
        den += qd * Zs[d];
        const float* Srow = &sm[d * 64];
        #pragma unroll
        for (int e = 0; e < 64; e++) num[e] += qd * Srow[e];
    }
    __syncthreads();
    float* Ksm = sm;
    float* Vsm = sm + 4096;
    for (int jt = 0; jt < CHUNK; jt += 64) {
        for (int idx = tid; idx < 1024; idx += 128) {
            int r = idx >> 4, c4 = (idx & 15) << 2;
            size_t base = ((size_t)(b * Lseq + c * CHUNK + jt + r)) * 3072 + h * 64 + c4;
            *(float4*)&Ksm[r * 64 + c4] = *(const float4*)&g_qkv[base + 1024];
            *(float4*)&Vsm[r * 64 + c4] = *(const float4*)&g_qkv[base + 2048];
        }
        __syncthreads();
        int jmax = i - jt + 1;
        if (jmax > 64) jmax = 64;
        for (int j = 0; j < jmax; j++) {
            const float* kr = &Ksm[j * 64];
            float s = 0.f;
            #pragma unroll
            for (int d = 0; d < 64; d++) s += q[d] * kr[d];
            den += s;
            const float* vr = &Vsm[j * 64];
            #pragma unroll
            for (int e = 0; e < 64; e++) num[e] += s * vr[e];
        }
        __syncthreads();
    }
    float invd = 1.f / fmaxf(den, 1e-6f);
    size_t obase = ((size_t)(b * Lseq + l)) * Emb + h * 64;
    #pragma unroll
    for (int e = 0; e < 64; e += 4) {
        float4 v = make_float4(num[e] * invd, num[e + 1] * invd, num[e + 2] * invd, num[e + 3] * invd);
        *(float4*)&g_attn[obase + e] = v;
    }
}

// ---------------- column-mean / dp scalar ----------------
__global__ void colmean_part_kernel() {
    int col = blockIdx.x * 256 + threadIdx.x, b = blockIdx.y, z = blockIdx.z;
    float s = 0.f;
    size_t base = ((size_t)b * Lseq + z * 128) * Emb + col;
    #pragma unroll 8
    for (int r = 0; r < 128; r++) s += g_h2[base + (size_t)r * Emb];
    g_part[(z * 2 + b) * Emb + col] = s;
}
__global__ void colmean_final_kernel() {
    int idx = blockIdx.x * 256 + threadIdx.x;
    float s = 0.f;
    for (int z = 0; z < 32; z++) s += g_part[(z * 2 + (idx >> 10)) * Emb + (idx & 1023)];
    g_xmean[idx] = s * (1.f / (float)Lseq);
}
__global__ void __launch_bounds__(256) dp_kernel(const float* __restrict__ w1,
                                                 const float* __restrict__ w2) {
    __shared__ float t[256];
    __shared__ float ratios[2];
    int tid = threadIdx.x;
    for (int b = 0; b < Bsz; b++) {
        float acc = 0.f;
        for (int e = 0; e < Emb; e++) acc += g_xmean[b * Emb + e] * w1[e * 256 + tid];
        float sg = 1.f / (1.f + expf(-acc));
        t[tid] = acc * sg;
        __syncthreads();
        if (tid == 0) {
            float s = 0.f;
            for (int j = 0; j < 256; j++) s += t[j] * w2[j];
            float r = 1.f / (1.f + expf(-s));
            float ratio = 1.f + (r - 0.5f);
            ratio = fminf(fmaxf(ratio, 0.5f), 1.5f);
            ratios[b] = ratio;
        }
        __syncthreads();
    }
    if (tid == 0) {
        float m = (ratios[0] + ratios[1]) * 0.5f;
        int sz = (int)floorf(3072.f * m);
        if (sz < 1) sz = 1;
        g_size[0] = sz;
    }
}

// ---------------- combine gate/up -> masked, RMS-normalized hidden ----------------
__global__ void __launch_bounds__(256) combine_kernel(const float* __restrict__ ghid) {
    int row = blockIdx.x, tid = threadIdx.x;
    int sz = g_size[0];
    __shared__ float buf[Ff];
    float local = 0.f;
    for (int c = tid; c < Ff; c += 256) {
        float hv = 0.f;
        if (c < sz) {
            float gv = g_gate[(size_t)row * Ff + c];
            float uv = g_up[(size_t)row * Ff + c];
            float sg = gv / (1.f + expf(-gv));
            hv = sg * uv;
            if (!isfinite(hv)) hv = 0.f;
        }
        buf[c] = hv;
        local += hv * hv;
    }
    float tot = blockReduceSum(local);
    float rms = sqrtf(tot / (float)sz + 1e-6f);
    rms = fminf(fmaxf(rms, 1e-6f), 1e6f);
    float inv = 1.f / rms;
    __syncthreads();
    for (int c = tid; c < Ff; c += 256) {
        float v = (c < sz) ? buf[c] * inv * ghid[c] : 0.f;
        g_hidden[(size_t)row * Ff + c] = v;
    }
}

// ---------------- host launch ----------------
extern "C" void kernel_launch(void* const* d_in, const int* in_sizes, int n_in,
                              void* d_out, int out_size) {
    const float* x = (const float*)d_in[0];
    const float* w_qkv = (const float*)d_in[1];
    const float* w_out = (const float*)d_in[2];
    const float* g1 = (const float*)d_in[3];
    const float* g2 = (const float*)d_in[4];
    const float* w_dp1 = (const float*)d_in[5];
    const float* w_dp2 = (const float*)d_in[6];
    const float* w_gate = (const float*)d_in[7];
    const float* w_up = (const float*)d_in[8];
    const float* w_down = (const float*)d_in[9];
    const float* ghid = (const float*)d_in[10];
    float* out = (float*)d_out;

    float *p_h, *p_qkv, *p_attn, *p_x2, *p_h2, *p_gate, *p_up, *p_hidden;
    int* p_size;
    cudaGetSymbolAddress((void**)&p_h, g_h);
    cudaGetSymbolAddress((void**)&p_qkv, g_qkv);
    cudaGetSymbolAddress((void**)&p_attn, g_attn);
    cudaGetSymbolAddress((void**)&p_x2, g_x2);
    cudaGetSymbolAddress((void**)&p_h2, g_h2);
    cudaGetSymbolAddress((void**)&p_gate, g_gate);
    cudaGetSymbolAddress((void**)&p_up, g_up);
    cudaGetSymbolAddress((void**)&p_hidden, g_hidden);
    cudaGetSymbolAddress((void**)&p_size, g_size);

    init_invfreq_kernel<<<1, 32>>>();

    // h = rms_norm(x, g1)
    rmsnorm_kernel<<<NTOK, 256>>>(x, g1, p_h);

    // qkv = h @ w_qkv
    tf32gemm_kernel<<<dim3(3 * Emb / 128, NTOK / 128), 256>>>(
        p_h, w_qkv, p_qkv, NTOK, 3 * Emb, Emb, nullptr, nullptr, nullptr);

    // RoPE + elu+1 on q,k
    rope_elu_kernel<<<(NTOK * Hh * 32 + 255) / 256, 256>>>(p_qkv);

    // linear attention (CHUNK=128)
    chunkstats_kernel<<<NCB, 256>>>();
    prefix_kernel<<<BHn, 256>>>();
    attn_out_kernel<<<NCB, 128>>>();

    // x2 = x + attn @ w_out
    tf32gemm_kernel<<<dim3(Emb / 128, NTOK / 128), 256>>>(
        p_attn, w_out, p_x2, NTOK, Emb, Emb, x, nullptr, nullptr);

    // h2 = rms_norm(x2, g2)
    rmsnorm_kernel<<<NTOK, 256>>>(p_x2, g2, p_h2);

    // adaptive size scalar
    colmean_part_kernel<<<dim3(Emb / 256, Bsz, 32), 256>>>();
    colmean_final_kernel<<<(Bsz * Emb) / 256, 256>>>();
    dp_kernel<<<1, 256>>>(w_dp1, w_dp2);

    // gate/up GEMMs with dynamic N cap
    tf32gemm_kernel<<<dim3(Ff / 128, NTOK / 128), 256>>>(
        p_h2, w_gate, p_gate, NTOK, Ff, Emb, nullptr, p_size, nullptr);
    tf32gemm_kernel<<<dim3(Ff / 128, NTOK / 128), 256>>>(
        p_h2, w_up, p_up, NTOK, Ff, Emb, nullptr, p_size, nullptr);

    // hidden = rmsnorm(silu(gate)*up masked)
    combine_kernel<<<NTOK, 256>>>(ghid);

    // out = x2 + hidden @ w_down  (K capped at size)
    tf32gemm_kernel<<<dim3(Emb / 128, NTOK / 128), 256>>>(
        p_hidden, w_down, out, NTOK, Emb, Ff, p_x2, nullptr, p_size);
}

// round 17
// speedup vs baseline: 1.1392x; 1.0051x over previous
#include <cuda_runtime.h>
#include <cuda_bf16.h>
#include <cstdint>
#include <math.h>

// ---------------- problem constants ----------------
#define Bsz 2
#define Lseq 4096
#define Emb 1024
#define Hh 16
#define Dd 64
#define Ff 4608
#define CHUNK 128
#define NC (Lseq / CHUNK)          // 32
#define NTOK (Bsz * Lseq)          // 8192
#define BHn 32
#define NCB (NC * BHn)             // 1024

// ---------------- scratch ----------------
__device__ float g_h[NTOK * Emb];
__device__ float g_qkv[NTOK * 3 * Emb];
__device__ float g_attn[NTOK * Emb];
__device__ float g_x2[NTOK * Emb];
__device__ float g_h2[NTOK * Emb];
__device__ float g_gate[NTOK * Ff];
__device__ float g_up[NTOK * Ff];
__device__ float g_hidden[NTOK * Ff];
__device__ float g_KV[NCB * Dd * Dd];
__device__ float g_Ksum[NCB * Dd];
__device__ float g_Sst[NCB * Dd * Dd];
__device__ float g_Zst[NCB * Dd];
__device__ float g_part[64 * Emb];
__device__ float g_xmean[Bsz * Emb];
__device__ int   g_size[1];
__device__ float g_invfreq[32];

// ---------------- helpers ----------------
__device__ __forceinline__ float blockReduceSum(float v) {
    __shared__ float red[32];
    #pragma unroll
    for (int o = 16; o > 0; o >>= 1) v += __shfl_down_sync(0xffffffffu, v, o);
    int lane = threadIdx.x & 31, w = threadIdx.x >> 5;
    if (lane == 0) red[w] = v;
    __syncthreads();
    int nw = blockDim.x >> 5;
    if (w == 0) {
        v = (lane < nw) ? red[lane] : 0.f;
        #pragma unroll
        for (int o = 16; o > 0; o >>= 1) v += __shfl_down_sync(0xffffffffu, v, o);
        if (lane == 0) red[0] = v;
    }
    __syncthreads();
    return red[0];
}

__device__ __forceinline__ float to_tf32(float x) {
    uint32_t u;
    asm("cvt.rna.tf32.f32 %0, %1;" : "=r"(u) : "f"(x));
    return __uint_as_float(u);
}

__device__ __forceinline__ void mma_tf32(
    float& d0, float& d1, float& d2, float& d3,
    float a0, float a1, float a2, float a3,
    float b0, float b1) {
    uint32_t A0 = __float_as_uint(a0), A1 = __float_as_uint(a1);
    uint32_t A2 = __float_as_uint(a2), A3 = __float_as_uint(a3);
    uint32_t B0 = __float_as_uint(b0), B1 = __float_as_uint(b1);
    asm("mma.sync.aligned.m16n8k8.row.col.f32.tf32.tf32.f32 "
        "{%0,%1,%2,%3}, {%4,%5,%6,%7}, {%8,%9}, {%0,%1,%2,%3};"
        : "+f"(d0), "+f"(d1), "+f"(d2), "+f"(d3)
        : "r"(A0), "r"(A1), "r"(A2), "r"(A3), "r"(B0), "r"(B1));
}

// ---------------- init: inv_freq table ----------------
__global__ void init_invfreq_kernel() {
    int i = threadIdx.x;
    if (i < 32) g_invfreq[i] = (float)exp(-((double)i / 32.0) * log(10000.0));
}

// ---------------- rms_norm ----------------
__global__ void __launch_bounds__(256) rmsnorm_kernel(const float* __restrict__ x,
                                                      const float* __restrict__ g,
                                                      float* __restrict__ out) {
    int row = blockIdx.x;
    int tid = threadIdx.x;
    const float4* xr = (const float4*)(x + (size_t)row * Emb);
    float4 v = xr[tid];
    if (!isfinite(v.x)) v.x = 0.f;
    if (!isfinite(v.y)) v.y = 0.f;
    if (!isfinite(v.z)) v.z = 0.f;
    if (!isfinite(v.w)) v.w = 0.f;
    float s = v.x * v.x + v.y * v.y + v.z * v.z + v.w * v.w;
    float tot = blockReduceSum(s);
    float rms = sqrtf(tot * (1.f / (float)Emb) + 1e-6f);
    rms = fminf(fmaxf(rms, 1e-6f), 1e6f);
    float inv = 1.f / rms;
    float4 gg = ((const float4*)g)[tid];
    float4 o;
    o.x = v.x * inv * gg.x; o.y = v.y * inv * gg.y;
    o.z = v.z * inv * gg.z; o.w = v.w * inv * gg.w;
    ((float4*)(out + (size_t)row * Emb))[tid] = o;
}

// ---------------- tf32 tensor-core GEMM (R6 winner, untouched) ----------------
#define LDSM 136
__global__ void __launch_bounds__(256, 2) tf32gemm_kernel(
    const float* __restrict__ A, const float* __restrict__ Bm, float* __restrict__ C,
    int M, int N, int K,
    const float* __restrict__ residual,
    const int* __restrict__ ncap, const int* __restrict__ kcap) {
    const int n0 = blockIdx.x * 128;
    const int m0 = blockIdx.y * 128;
    if (ncap && n0 >= *ncap) return;
    int kend = K;
    if (kcap) {
        int kc = (*kcap + 15) & ~15;
        if (kc < 16) kc = 16;
        if (kc < kend) kend = kc;
    }

    __shared__ __align__(16) float As[2][16 * LDSM];
    __shared__ __align__(16) float Bs[2][16 * LDSM];

    const int tid = threadIdx.x;
    const int lane = tid & 31;
    const int warp = tid >> 5;
    const int wm = (warp & 3) * 32;
    const int wn = (warp >> 2) * 64;
    const int g = lane >> 2;
    const int t = lane & 3;

    const int aRow = tid >> 2;
    const int aCol = (tid & 3) << 2;
    const int bRow = tid >> 5;
    const int bCol = (tid & 31) << 2;

    const float* Ap0 = A + (size_t)(m0 + aRow) * K + aCol;
    const float* Ap1 = A + (size_t)(m0 + aRow + 64) * K + aCol;
    const float* Bp0 = Bm + (size_t)bRow * N + n0 + bCol;
    const float* Bp1 = Bm + (size_t)(bRow + 8) * N + n0 + bCol;

    float acc[2][8][4];
    #pragma unroll
    for (int mi = 0; mi < 2; mi++)
        #pragma unroll
        for (int ni = 0; ni < 8; ni++)
            #pragma unroll
            for (int r = 0; r < 4; r++) acc[mi][ni][r] = 0.f;

    float4 aReg0, aReg1, bReg0, bReg1;

    auto gload = [&](int k) {
        aReg0 = *(const float4*)(Ap0 + k);
        aReg1 = *(const float4*)(Ap1 + k);
        bReg0 = *(const float4*)(Bp0 + (size_t)k * N);
        bReg1 = *(const float4*)(Bp1 + (size_t)k * N);
    };

    auto sstore = [&](int buf) {
        As[buf][(aCol + 0) * LDSM + aRow] = to_tf32(aReg0.x);
        As[buf][(aCol + 1) * LDSM + aRow] = to_tf32(aReg0.y);
        As[buf][(aCol + 2) * LDSM + aRow] = to_tf32(aReg0.z);
        As[buf][(aCol + 3) * LDSM + aRow] = to_tf32(aReg0.w);
        As[buf][(aCol + 0) * LDSM + aRow + 64] = to_tf32(aReg1.x);
        As[buf][(aCol + 1) * LDSM + aRow + 64] = to_tf32(aReg1.y);
        As[buf][(aCol + 2) * LDSM + aRow + 64] = to_tf32(aReg1.z);
        As[buf][(aCol + 3) * LDSM + aRow + 64] = to_tf32(aReg1.w);
        float4 b0 = make_float4(to_tf32(bReg0.x), to_tf32(bReg0.y), to_tf32(bReg0.z), to_tf32(bReg0.w));
        float4 b1 = make_float4(to_tf32(bReg1.x), to_tf32(bReg1.y), to_tf32(bReg1.z), to_tf32(bReg1.w));
        *(float4*)&Bs[buf][bRow * LDSM + bCol] = b0;
        *(float4*)&Bs[buf][(bRow + 8) * LDSM + bCol] = b1;
    };

    auto compute = [&](int buf) {
        const float* Asb = As[buf];
        const float* Bsb = Bs[buf];
        #pragma unroll
        for (int ks = 0; ks < 2; ks++) {
            const int k0 = ks * 8;
            float af[2][4];
            #pragma unroll
            for (int mi = 0; mi < 2; mi++) {
                int mrow = wm + mi * 16 + g;
                af[mi][0] = Asb[(k0 + t) * LDSM + mrow];
                af[mi][1] = Asb[(k0 + t) * LDSM + mrow + 8];
                af[mi][2] = Asb[(k0 + t + 4) * LDSM + mrow];
                af[mi][3] = Asb[(k0 + t + 4) * LDSM + mrow + 8];
            }
            float bf[8][2];
            #pragma unroll
            for (int ni = 0; ni < 8; ni++) {
                int ncol = wn + ni * 8 + g;
                bf[ni][0] = Bsb[(k0 + t) * LDSM + ncol];
                bf[ni][1] = Bsb[(k0 + t + 4) * LDSM + ncol];
            }
            #pragma unroll
            for (int mi = 0; mi < 2; mi++)
                #pragma unroll
                for (int ni = 0; ni < 8; ni++)
                    mma_tf32(acc[mi][ni][0], acc[mi][ni][1], acc[mi][ni][2], acc[mi][ni][3],
                             af[mi][0], af[mi][1], af[mi][2], af[mi][3],
                             bf[ni][0], bf[ni][1]);
        }
    };

    gload(0);
    sstore(0);
    __syncthreads();
    int buf = 0;
    for (int k = 16; k < kend; k += 16) {
        gload(k);
        compute(buf);
        sstore(buf ^ 1);
        __syncthreads();
        buf ^= 1;
    }
    compute(buf);

    #pragma unroll
    for (int mi = 0; mi < 2; mi++) {
        #pragma unroll
        for (int ni = 0; ni < 8; ni++) {
            int row0 = m0 + wm + mi * 16 + g;
            int col = n0 + wn + ni * 8 + t * 2;
            float2 v0 = make_float2(acc[mi][ni][0], acc[mi][ni][1]);
            float2 v1 = make_float2(acc[mi][ni][2], acc[mi][ni][3]);
            if (residual) {
                float2 r0 = *(const float2*)&residual[(size_t)row0 * N + col];
                float2 r1 = *(const float2*)&residual[(size_t)(row0 + 8) * N + col];
                v0.x += r0.x; v0.y += r0.y;
                v1.x += r1.x; v1.y += r1.y;
            }
            *(float2*)&C[(size_t)row0 * N + col] = v0;
            *(float2*)&C[(size_t)(row0 + 8) * N + col] = v1;
        }
    }
}

// ---------------- RoPE + elu+1 on q,k ----------------
__global__ void __launch_bounds__(256) rope_elu_kernel(float* __restrict__ qkv) {
    int idx = blockIdx.x * blockDim.x + threadIdx.x;
    if (idx >= NTOK * Hh * 32) return;
    int p = idx & 31, h = (idx >> 5) & 15, t = idx >> 9;
    int l = t & (Lseq - 1), d0 = 2 * p;
    float a0 = (float)l * g_invfreq[d0 & 31];
    float a1 = (float)l * g_invfreq[(d0 + 1) & 31];
    float s0, c0, s1, c1;
    sincosf(a0, &s0, &c0);
    sincosf(a1, &s1, &c1);
    size_t base = (size_t)t * 3072 + h * 64 + d0;
    #pragma unroll
    for (int s = 0; s < 2; s++) {
        float va = qkv[base + s * 1024], vb = qkv[base + s * 1024 + 1];
        float r0 = va * c0 - vb * s0, r1 = vb * c1 + va * s1;
        r0 = (r0 > 0.f) ? (r0 + 1.f) : expf(r0);
        r1 = (r1 > 0.f) ? (r1 + 1.f) : expf(r1);
        qkv[base + s * 1024] = r0;
        qkv[base + s * 1024 + 1] = r1;
    }
}

// ---------------- per-chunk K^T V and sum(K) (CHUNK=128) ----------------
__global__ void __launch_bounds__(256) chunkstats_kernel() {
    int cb = blockIdx.x, bh = cb & 31, c = cb >> 5;
    int b = bh >> 4, h = bh & 15, tid = threadIdx.x;
    __shared__ __align__(16) float Ks[32][64], Vs[32][64];
    const int d0 = (tid >> 4) * 4, e0 = (tid & 15) * 4;
    float acc[4][4];
    #pragma unroll
    for (int i = 0; i < 4; i++)
        #pragma unroll
        for (int j = 0; j < 4; j++) acc[i][j] = 0.f;
    float ks = 0.f;
    for (int lt = 0; lt < CHUNK; lt += 32) {
        int idx = tid;
        #pragma unroll
        for (int it = 0; it < 2; it++, idx += 256) {
            int r = idx >> 4, c4 = (idx & 15) << 2;
            size_t base = ((size_t)(b * Lseq + c * CHUNK + lt + r)) * 3072 + h * 64 + c4;
            *(float4*)&Ks[r][c4] = *(const float4*)&g_qkv[base + 1024];
            *(float4*)&Vs[r][c4] = *(const float4*)&g_qkv[base + 2048];
        }
        __syncthreads();
        #pragma unroll 4
        for (int ll = 0; ll < 32; ll++) {
            float kd[4], ve[4];
            #pragma unroll
            for (int i = 0; i < 4; i++) kd[i] = Ks[ll][d0 + i];
            #pragma unroll
            for (int j = 0; j < 4; j++) ve[j] = Vs[ll][e0 + j];
            #pragma unroll
            for (int i = 0; i < 4; i++)
                #pragma unroll
                for (int j = 0; j < 4; j++) acc[i][j] += kd[i] * ve[j];
        }
        if (tid < 64) {
            #pragma unroll 4
            for (int ll = 0; ll < 32; ll++) ks += Ks[ll][tid];
        }
        __syncthreads();
    }
    size_t off = (size_t)cb * (Dd * Dd);
    #pragma unroll
    for (int i = 0; i < 4; i++)
        #pragma unroll
        for (int j = 0; j < 4; j++)
            g_KV[off + (d0 + i) * 64 + e0 + j] = acc[i][j];
    if (tid < 64) g_Ksum[(size_t)cb * 64 + tid] = ks;
}

// ---------------- exclusive prefix over NC=32 chunks per (b,h) ----------------
__global__ void __launch_bounds__(256) prefix_kernel() {
    int bh = blockIdx.x, tid = threadIdx.x;
    float acc[16];
    #pragma unroll
    for (int t = 0; t < 16; t++) acc[t] = 0.f;
    for (int c = 0; c < NC; c++) {
        size_t off = (size_t)(c * 32 + bh) * (Dd * Dd);
        #pragma unroll
        for (int t = 0; t < 16; t++) {
            int e = tid + t * 256;
            g_Sst[off + e] = acc[t];
            acc[t] += g_KV[off + e];
        }
    }
    if (tid < 64) {
        float az = 0.f;
        for (int c = 0; c < NC; c++) {
            size_t off = (size_t)(c * 32 + bh) * 64 + tid;
            g_Zst[off] = az;
            az += g_Ksum[off];
        }
    }
}

// ---------------- attention output (CHUNK=128, float4 smem reads) ----------------
__global__ void __launch_bounds__(128) attn_out_kernel() {
    int cb = blockIdx.x, bh = cb & 31, c = cb >> 5;
    int b = bh >> 4, h = bh & 15, tid = threadIdx.x;
    int i = tid, l = c * CHUNK + i;
    __shared__ __align__(16) float sm[2 * 64 * 64];
    __shared__ float Zs[64];
    {
        size_t off = (size_t)cb * (Dd * Dd);
        for (int t = tid; t < 4096; t += 128) sm[t] = g_Sst[off + t];
        if (tid < 64) Zs[tid] = g_Zst[(size_t)cb * 64 + tid];
    }
    size_t qbase = ((size_t)(b * Lseq + l)) * 3072 + h * 64;
    float q[64];
    #pragma unroll
    for (int d = 0; d < 64; d += 4) {
        float4 v = *(const float4*)&g_qkv[qbase + d];
        q[d] = v.x; q[d + 1] = v.y; q[d + 2] = v.z; q[d + 3] = v.w;
    }
    __syncthreads();
    float num[64];
    #pragma unroll
    for (int e = 0; e < 64; e++) num[e] = 0.f;
    float den = 0.f;
    // Q @ S, Q @ Z — float4 Srow reads (same per-element order)
    for (int d = 0; d < 64; d++) {
        float qd = __ldg(&g_qkv[qbase + d]);
        den += qd * Zs[d];
        const float4* Srow = (const float4*)&sm[d * 64];
        #pragma unroll
        for (int e4 = 0; e4 < 16; e4++) {
            float4 sv = Srow[e4];
            num[e4 * 4 + 0] += qd * sv.x;
            num[e4 * 4 + 1] += qd * sv.y;
            num[e4 * 4 + 2] += qd * sv.z;
            num[e4 * 4 + 3] += qd * sv.w;
        }
    }
    __syncthreads();
    float* Ksm = sm;
    float* Vsm = sm + 4096;
    for (int jt = 0; jt < CHUNK; jt += 64) {
        for (int idx = tid; idx < 1024; idx += 128) {
            int r = idx >> 4, c4 = (idx & 15) << 2;
            size_t base = ((size_t)(b * Lseq + c * CHUNK + jt + r)) * 3072 + h * 64 + c4;
            *(float4*)&Ksm[r * 64 + c4] = *(const float4*)&g_qkv[base + 1024];
            *(float4*)&Vsm[r * 64 + c4] = *(const float4*)&g_qkv[base + 2048];
        }
        __syncthreads();
        int jmax = i - jt + 1;
        if (jmax > 64) jmax = 64;
        for (int j = 0; j < jmax; j++) {
            const float4* kr = (const float4*)&Ksm[j * 64];
            float s = 0.f;
            #pragma unroll
            for (int d4 = 0; d4 < 16; d4++) {
                float4 kv = kr[d4];
                s += q[d4 * 4 + 0] * kv.x;
                s += q[d4 * 4 + 1] * kv.y;
                s += q[d4 * 4 + 2] * kv.z;
                s += q[d4 * 4 + 3] * kv.w;
            }
            den += s;
            const float4* vr = (const float4*)&Vsm[j * 64];
            #pragma unroll
            for (int e4 = 0; e4 < 16; e4++) {
                float4 vv = vr[e4];
                num[e4 * 4 + 0] += s * vv.x;
                num[e4 * 4 + 1] += s * vv.y;
                num[e4 * 4 + 2] += s * vv.z;
                num[e4 * 4 + 3] += s * vv.w;
            }
        }
        __syncthreads();
    }
    float invd = 1.f / fmaxf(den, 1e-6f);
    size_t obase = ((size_t)(b * Lseq + l)) * Emb + h * 64;
    #pragma unroll
    for (int e = 0; e < 64; e += 4) {
        float4 v = make_float4(num[e] * invd, num[e + 1] * invd, num[e + 2] * invd, num[e + 3] * invd);
        *(float4*)&g_attn[obase + e] = v;
    }
}

// ---------------- column-mean / dp scalar ----------------
__global__ void colmean_part_kernel() {
    int col = blockIdx.x * 256 + threadIdx.x, b = blockIdx.y, z = blockIdx.z;
    float s = 0.f;
    size_t base = ((size_t)b * Lseq + z * 128) * Emb + col;
    #pragma unroll 8
    for (int r = 0; r < 128; r++) s += g_h2[base + (size_t)r * Emb];
    g_part[(z * 2 + b) * Emb + col] = s;
}
__global__ void colmean_final_kernel() {
    int idx = blockIdx.x * 256 + threadIdx.x;
    float s = 0.f;
    for (int z = 0; z < 32; z++) s += g_part[(z * 2 + (idx >> 10)) * Emb + (idx & 1023)];
    g_xmean[idx] = s * (1.f / (float)Lseq);
}
__global__ void __launch_bounds__(256) dp_kernel(const float* __restrict__ w1,
                                                 const float* __restrict__ w2) {
    __shared__ float t[256];
    __shared__ float ratios[2];
    int tid = threadIdx.x;
    for (int b = 0; b < Bsz; b++) {
        float acc = 0.f;
        for (int e = 0; e < Emb; e++) acc += g_xmean[b * Emb + e] * w1[e * 256 + tid];
        float sg = 1.f / (1.f + expf(-acc));
        t[tid] = acc * sg;
        __syncthreads();
        if (tid == 0) {
            float s = 0.f;
            for (int j = 0; j < 256; j++) s += t[j] * w2[j];
            float r = 1.f / (1.f + expf(-s));
            float ratio = 1.f + (r - 0.5f);
            ratio = fminf(fmaxf(ratio, 0.5f), 1.5f);
            ratios[b] = ratio;
        }
        __syncthreads();
    }
    if (tid == 0) {
        float m = (ratios[0] + ratios[1]) * 0.5f;
        int sz = (int)floorf(3072.f * m);
        if (sz < 1) sz = 1;
        g_size[0] = sz;
    }
}

// ---------------- combine: write only [0, kcap16) of hidden ----------------
__global__ void __launch_bounds__(256) combine_kernel(const float* __restrict__ ghid) {
    int row = blockIdx.x, tid = threadIdx.x;
    int sz = g_size[0];
    int cap = (sz + 15) & ~15;
    if (cap < 16) cap = 16;
    if (cap > Ff) cap = Ff;
    __shared__ float buf[Ff];
    float local = 0.f;
    for (int c = tid; c < Ff; c += 256) {
        float hv = 0.f;
        if (c < sz) {
            float gv = g_gate[(size_t)row * Ff + c];
            float uv = g_up[(size_t)row * Ff + c];
            float sg = gv / (1.f + expf(-gv));
            hv = sg * uv;
            if (!isfinite(hv)) hv = 0.f;
        }
        buf[c] = hv;
        local += hv * hv;
    }
    float tot = blockReduceSum(local);
    float rms = sqrtf(tot / (float)sz + 1e-6f);
    rms = fminf(fmaxf(rms, 1e-6f), 1e6f);
    float inv = 1.f / rms;
    __syncthreads();
    // down-GEMM reads only k < cap (kcap rounds sz up to 16); beyond-cap never read
    for (int c = tid; c < cap; c += 256) {
        float v = (c < sz) ? buf[c] * inv * ghid[c] : 0.f;
        g_hidden[(size_t)row * Ff + c] = v;
    }
}

// ---------------- host launch ----------------
extern "C" void kernel_launch(void* const* d_in, const int* in_sizes, int n_in,
                              void* d_out, int out_size) {
    const float* x = (const float*)d_in[0];
    const float* w_qkv = (const float*)d_in[1];
    const float* w_out = (const float*)d_in[2];
    const float* g1 = (const float*)d_in[3];
    const float* g2 = (const float*)d_in[4];
    const float* w_dp1 = (const float*)d_in[5];
    const float* w_dp2 = (const float*)d_in[6];
    const float* w_gate = (const float*)d_in[7];
    const float* w_up = (const float*)d_in[8];
    const float* w_down = (const float*)d_in[9];
    const float* ghid = (const float*)d_in[10];
    float* out = (float*)d_out;

    float *p_h, *p_qkv, *p_attn, *p_x2, *p_h2, *p_gate, *p_up, *p_hidden;
    int* p_size;
    cudaGetSymbolAddress((void**)&p_h, g_h);
    cudaGetSymbolAddress((void**)&p_qkv, g_qkv);
    cudaGetSymbolAddress((void**)&p_attn, g_attn);
    cudaGetSymbolAddress((void**)&p_x2, g_x2);
    cudaGetSymbolAddress((void**)&p_h2, g_h2);
    cudaGetSymbolAddress((void**)&p_gate, g_gate);
    cudaGetSymbolAddress((void**)&p_up, g_up);
    cudaGetSymbolAddress((void**)&p_hidden, g_hidden);
    cudaGetSymbolAddress((void**)&p_size, g_size);

    init_invfreq_kernel<<<1, 32>>>();

    // h = rms_norm(x, g1)
    rmsnorm_kernel<<<NTOK, 256>>>(x, g1, p_h);

    // qkv = h @ w_qkv
    tf32gemm_kernel<<<dim3(3 * Emb / 128, NTOK / 128), 256>>>(
        p_h, w_qkv, p_qkv, NTOK, 3 * Emb, Emb, nullptr, nullptr, nullptr);

    // RoPE + elu+1 on q,k
    rope_elu_kernel<<<(NTOK * Hh * 32 + 255) / 256, 256>>>(p_qkv);

    // linear attention (CHUNK=128)
    chunkstats_kernel<<<NCB, 256>>>();
    prefix_kernel<<<BHn, 256>>>();
    attn_out_kernel<<<NCB, 128>>>();

    // x2 = x + attn @ w_out
    tf32gemm_kernel<<<dim3(Emb / 128, NTOK / 128), 256>>>(
        p_attn, w_out, p_x2, NTOK, Emb, Emb, x, nullptr, nullptr);

    // h2 = rms_norm(x2, g2)
    rmsnorm_kernel<<<NTOK, 256>>>(p_x2, g2, p_h2);

    // adaptive size scalar
    colmean_part_kernel<<<dim3(Emb / 256, Bsz, 32), 256>>>();
    colmean_final_kernel<<<(Bsz * Emb) / 256, 256>>>();
    dp_kernel<<<1, 256>>>(w_dp1, w_dp2);

    // gate/up GEMMs with dynamic N cap
    tf32gemm_kernel<<<dim3(Ff / 128, NTOK / 128), 256>>>(
        p_h2, w_gate, p_gate, NTOK, Ff, Emb, nullptr, p_size, nullptr);
    tf32gemm_kernel<<<dim3(Ff / 128, NTOK / 128), 256>>>(
        p_h2, w_up, p_up, NTOK, Ff, Emb, nullptr, p_size, nullptr);

    // hidden = rmsnorm(silu(gate)*up masked)
    combine_kernel<<<NTOK, 256>>>(ghid);

    // out = x2 + hidden @ w_down  (K capped at size)
    tf32gemm_kernel<<<dim3(Emb / 128, NTOK / 128), 256>>>(
        p_hidden, w_down, out, NTOK, Emb, Ff, p_x2, nullptr, p_size);
}